// round 6
// baseline (speedup 1.0000x reference)
#include <cuda_runtime.h>
#include <cuda_bf16.h>
#include <math.h>

namespace {

constexpr int L    = 10;
constexpr int NH   = L * L;      // 100 harmonics
constexpr int CHK  = NH / 4;     // 25 float4 per point
constexpr int TILE = 32;         // points per warp-tile
constexpr int TPB  = 32;         // one warp per block
constexpr int NBLK = 1184;       // 8 resident blocks/SM * 148 SMs
constexpr double PI_D = 3.141592653589793238462643383279502884;

// ---- compile-time math (all constants folded to FFMA immediates) ----
constexpr double csqrt(double x) {
    double r = x > 1.0 ? x : 1.0;
    for (int i = 0; i < 100; ++i) r = 0.5 * (r + x / r);
    return r;
}
constexpr double factd(int n) {
    double r = 1.0;
    for (int i = 2; i <= n; ++i) r *= (double)i;
    return r;
}
constexpr double SQRT2_D = csqrt(2.0);
constexpr double Kd(int l, int m) {
    return csqrt((2.0 * l + 1.0) / (4.0 * PI_D) * factd(l - m) / factd(l + m));
}
constexpr double Kh(int l, int m) {
    return (m > 0 ? SQRT2_D : 1.0) * Kd(l, m);
}

struct Tabs {
    float k00;
    float dm[L];
    float em[L];
    float A[L][L];
    float B[L][L];
};

constexpr Tabs make_tabs() {
    Tabs t{};
    t.k00 = (float)Kh(0, 0);
    for (int m = 1; m < L; ++m)
        t.dm[m] = (float)(-(2.0 * m - 1.0) * Kh(m, m) / Kh(m - 1, m - 1));
    for (int m = 0; m + 1 < L; ++m)
        t.em[m] = (float)((2.0 * m + 1.0) * Kh(m + 1, m) / Kh(m, m));
    for (int m = 0; m < L; ++m)
        for (int l = m + 2; l < L; ++l) {
            t.A[l][m] = (float)((2.0 * l - 1.0) / (double)(l - m) * Kh(l, m) / Kh(l - 1, m));
            t.B[l][m] = (float)(-(l + m - 1.0) / (double)(l - m) * Kh(l, m) / Kh(l - 2, m));
        }
    return t;
}
constexpr Tabs TB = make_tabs();

template <int I> struct IC { static constexpr int v = I; };
template <int S, int E, class F>
__device__ __forceinline__ void unrolled(F&& f) {
    if constexpr (S < E) {
        f(IC<S>{});
        unrolled<S + 1, E>(static_cast<F&&>(f));
    }
}

__device__ __forceinline__ unsigned smem_u32(const void* p) {
    unsigned a;
    asm("{ .reg .u64 t; cvta.to.shared.u64 t, %1; cvt.u32.u64 %0, t; }"
        : "=r"(a) : "l"(p));
    return a;
}

} // namespace

__global__ __launch_bounds__(TPB) void sh_kernel(const float2* __restrict__ ll,
                                                 float* __restrict__ out, int N) {
    // double-buffered staging: 2 x 32 points x 25 float4 = 25600 B
    __shared__ __align__(16) float4 buf[2][TILE * CHK];

    const int lane   = threadIdx.x;
    const int nTiles = (N + TILE - 1) / TILE;
    int b = 0;

    for (int tile = blockIdx.x; tile < nTiles; tile += gridDim.x) {
        const int p = tile * TILE + lane;

        // ---------------- compute: all 100 values into registers ----------------
        float y[NH];
        {
            float2 v = (p < N) ? ll[p] : ll[0];
            const float phi = (v.x + 180.0f) * 0.017453292519943295f;
            const float th  = (v.y + 90.0f)  * 0.017453292519943295f;
            float s, x, s1, c1;
            __sincosf(th,  &s,  &x);    // s = sin(theta), x = cos(theta)
            __sincosf(phi, &s1, &c1);

            float Qmm = 0.0f;
            float cm = 1.0f, smv = 0.0f;

            unrolled<0, L>([&](auto mI) {
                constexpr int m = decltype(mI)::v;

                if constexpr (m == 0) {
                    Qmm = TB.k00;
                } else if constexpr (m == 1) {
                    constexpr float d = TB.dm[1];
                    Qmm = d * (s * Qmm);
                    cm = c1; smv = s1;
                } else {
                    constexpr float d = TB.dm[m];
                    Qmm = d * (s * Qmm);
                    const float cn = fmaf(cm, c1, -(smv * s1));
                    const float sn = fmaf(smv, c1,  (cm * s1));
                    cm = cn; smv = sn;
                }

                if constexpr (m == 0) {
                    y[0] = Qmm;
                } else {
                    y[m * m + 2 * m] = Qmm * cm;
                    y[m * m]         = Qmm * smv;
                }

                if constexpr (m + 1 < L) {
                    constexpr float e = TB.em[m];
                    float Q1 = e * (x * Qmm);
                    constexpr int l1 = m + 1;
                    if constexpr (m == 0) {
                        y[l1 * l1 + l1] = Q1;
                    } else {
                        y[l1 * l1 + l1 + m] = Q1 * cm;
                        y[l1 * l1 + l1 - m] = Q1 * smv;
                    }
                    float Q2 = Qmm;
                    unrolled<m + 2, L>([&](auto lI) {
                        constexpr int l = decltype(lI)::v;
                        constexpr float a = TB.A[l][m];
                        constexpr float b2 = TB.B[l][m];
                        const float Qn = fmaf(x * Q1, a, b2 * Q2);
                        if constexpr (m == 0) {
                            y[l * l + l] = Qn;
                        } else {
                            y[l * l + l + m] = Qn * cm;
                            y[l * l + l - m] = Qn * smv;
                        }
                        Q2 = Q1; Q1 = Qn;
                    });
                }
            });
        }

        // buffer b was handed to TMA two iterations ago; ensure that read finished.
        // Outstanding groups <= 1 means all but the most recent commit have completed.
        if (lane == 0)
            asm volatile("cp.async.bulk.wait_group.read 1;" ::: "memory");
        __syncwarp();

        // stage point-major: buf[b][lane*25 + q]  (banks 4(lane+q)%32 -> conflict-free)
        {
            float4* rp = buf[b] + lane * CHK;
            unrolled<0, CHK>([&](auto qI) {
                constexpr int q = decltype(qI)::v;
                rp[q] = make_float4(y[4 * q], y[4 * q + 1], y[4 * q + 2], y[4 * q + 3]);
            });
        }
        __syncwarp();

        // async bulk store smem -> gmem (contiguous 32 rows), no wait here
        if (lane == 0) {
            asm volatile("fence.proxy.async.shared::cta;" ::: "memory");
            const int npts   = min(TILE, N - tile * TILE);
            const int nbytes = npts * NH * 4;
            float* g = out + (size_t)tile * TILE * NH;
            const unsigned ssrc = smem_u32(buf[b]);
            asm volatile(
                "cp.async.bulk.global.shared::cta.bulk_group [%0], [%1], %2;"
                :: "l"(g), "r"(ssrc), "r"(nbytes) : "memory");
            asm volatile("cp.async.bulk.commit_group;" ::: "memory");
        }
        b ^= 1;
    }

    // drain all outstanding TMA reads before smem is torn down
    if (lane == 0)
        asm volatile("cp.async.bulk.wait_group.read 0;" ::: "memory");
    __syncwarp();
}

extern "C" void kernel_launch(void* const* d_in, const int* in_sizes, int n_in,
                              void* d_out, int out_size) {
    const float2* ll = (const float2*)d_in[0];
    float* out = (float*)d_out;
    const int N = in_sizes[0] / 2;
    const int nTiles = (N + TILE - 1) / TILE;
    const int grid = nTiles < NBLK ? nTiles : NBLK;
    sh_kernel<<<grid, TPB>>>(ll, out, N);
}

// round 7
// speedup vs baseline: 1.2522x; 1.2522x over previous
#include <cuda_runtime.h>
#include <cuda_bf16.h>
#include <math.h>

namespace {

constexpr int L    = 10;
constexpr int NH   = L * L;      // 100 harmonics
constexpr int NPB  = 32;         // one warp per block, 1 point/thread
constexpr int CHK  = NH / 4;     // 25 float4 chunks per point
constexpr int QSTR = 132;        // words between chunk-rows (132 mod 32 = 4 -> conflict-free)
constexpr double PI_D = 3.141592653589793238462643383279502884;

// ---- compile-time math (all constants folded to FFMA immediates) ----
constexpr double csqrt(double x) {
    double r = x > 1.0 ? x : 1.0;
    for (int i = 0; i < 100; ++i) r = 0.5 * (r + x / r);
    return r;
}
constexpr double factd(int n) {
    double r = 1.0;
    for (int i = 2; i <= n; ++i) r *= (double)i;
    return r;
}
constexpr double SQRT2_D = csqrt(2.0);
constexpr double Kd(int l, int m) {
    return csqrt((2.0 * l + 1.0) / (4.0 * PI_D) * factd(l - m) / factd(l + m));
}
constexpr double Kh(int l, int m) {
    return (m > 0 ? SQRT2_D : 1.0) * Kd(l, m);
}

struct Tabs {
    float k00;
    float dm[L];
    float em[L];
    float A[L][L];
    float B[L][L];
};

constexpr Tabs make_tabs() {
    Tabs t{};
    t.k00 = (float)Kh(0, 0);
    for (int m = 1; m < L; ++m)
        t.dm[m] = (float)(-(2.0 * m - 1.0) * Kh(m, m) / Kh(m - 1, m - 1));
    for (int m = 0; m + 1 < L; ++m)
        t.em[m] = (float)((2.0 * m + 1.0) * Kh(m + 1, m) / Kh(m, m));
    for (int m = 0; m < L; ++m)
        for (int l = m + 2; l < L; ++l) {
            t.A[l][m] = (float)((2.0 * l - 1.0) / (double)(l - m) * Kh(l, m) / Kh(l - 1, m));
            t.B[l][m] = (float)(-(l + m - 1.0) / (double)(l - m) * Kh(l, m) / Kh(l - 2, m));
        }
    return t;
}
constexpr Tabs TB = make_tabs();

template <int I> struct IC { static constexpr int v = I; };
template <int S, int E, class F>
__device__ __forceinline__ void unrolled(F&& f) {
    if constexpr (S < E) {
        f(IC<S>{});
        unrolled<S + 1, E>(static_cast<F&&>(f));
    }
}

} // namespace

__global__ __launch_bounds__(NPB) void sh_kernel(const float2* __restrict__ ll,
                                                 float* __restrict__ out, int N) {
    __shared__ float sw[CHK * QSTR];   // 3300 words = 13200 B per block (1 warp)

    const int lane = threadIdx.x;      // == lane id (32-thread blocks)
    const int p0   = blockIdx.x * NPB;
    const int p    = p0 + lane;

    // ---------------- compute phase: all 100 values into registers ----------------
    float y[NH];

    {
        float2 v = (p < N) ? ll[p] : ll[0];
        const float phi = (v.x + 180.0f) * 0.017453292519943295f;
        const float th  = (v.y + 90.0f)  * 0.017453292519943295f;
        float s, x, s1, c1;
        __sincosf(th,  &s,  &x);     // s = sin(theta), x = cos(theta)
        __sincosf(phi, &s1, &c1);

        float Qmm = 0.0f;
        float cm = 1.0f, smv = 0.0f;

        unrolled<0, L>([&](auto mI) {
            constexpr int m = decltype(mI)::v;

            if constexpr (m == 0) {
                Qmm = TB.k00;
            } else if constexpr (m == 1) {
                constexpr float d = TB.dm[1];
                Qmm = d * (s * Qmm);
                cm = c1; smv = s1;
            } else {
                constexpr float d = TB.dm[m];
                Qmm = d * (s * Qmm);
                const float cn = fmaf(cm, c1, -(smv * s1));
                const float sn = fmaf(smv, c1,  (cm * s1));
                cm = cn; smv = sn;
            }

            if constexpr (m == 0) {
                y[0] = Qmm;
            } else {
                y[m * m + 2 * m] = Qmm * cm;
                y[m * m]         = Qmm * smv;
            }

            if constexpr (m + 1 < L) {
                constexpr float e = TB.em[m];
                float Q1 = e * (x * Qmm);
                constexpr int l1 = m + 1;
                if constexpr (m == 0) {
                    y[l1 * l1 + l1] = Q1;
                } else {
                    y[l1 * l1 + l1 + m] = Q1 * cm;
                    y[l1 * l1 + l1 - m] = Q1 * smv;
                }
                float Q2 = Qmm;
                unrolled<m + 2, L>([&](auto lI) {
                    constexpr int l = decltype(lI)::v;
                    constexpr float a = TB.A[l][m];
                    constexpr float b = TB.B[l][m];
                    const float Qn = fmaf(x * Q1, a, b * Q2);
                    if constexpr (m == 0) {
                        y[l * l + l] = Qn;
                    } else {
                        y[l * l + l + m] = Qn * cm;
                        y[l * l + l - m] = Qn * smv;
                    }
                    Q2 = Q1; Q1 = Qn;
                });
            }
        });
    }

    // 25 x STS.128, chunk-major: sw[q*QSTR + lane*4]  (banks 4(q+lane)%32 -> conflict-free)
    unrolled<0, CHK>([&](auto qI) {
        constexpr int q = decltype(qI)::v;
        *reinterpret_cast<float4*>(sw + q * QSTR + lane * 4) =
            make_float4(y[4 * q], y[4 * q + 1], y[4 * q + 2], y[4 * q + 3]);
    });

    __syncwarp();

    // ---------------- copy phase: 25 x (LDS.128 + STG.128), fully coalesced ----------------
    float* og = out + (size_t)p0 * NH;

    if (p0 + 32 <= N) {
        #pragma unroll 5
        for (int i = 0; i < CHK; ++i) {
            const int k  = i * 32 + lane;     // flat float4 index within tile (0..799)
            const int pf = k / 25;
            const int q  = k - pf * 25;
            const float4 v = *reinterpret_cast<const float4*>(sw + q * QSTR + pf * 4);
            __stcs(reinterpret_cast<float4*>(og + 4 * k), v);
        }
    } else {
        #pragma unroll 5
        for (int i = 0; i < CHK; ++i) {
            const int k  = i * 32 + lane;
            const int pf = k / 25;
            const int q  = k - pf * 25;
            if (p0 + pf < N) {
                const float4 v = *reinterpret_cast<const float4*>(sw + q * QSTR + pf * 4);
                __stcs(reinterpret_cast<float4*>(og + 4 * k), v);
            }
        }
    }
}

extern "C" void kernel_launch(void* const* d_in, const int* in_sizes, int n_in,
                              void* d_out, int out_size) {
    const float2* ll = (const float2*)d_in[0];
    float* out = (float*)d_out;
    const int N = in_sizes[0] / 2;
    const int grid = (N + NPB - 1) / NPB;
    sh_kernel<<<grid, NPB>>>(ll, out, N);
}

// round 9
// speedup vs baseline: 1.2676x; 1.0123x over previous
#include <cuda_runtime.h>
#include <cuda_bf16.h>
#include <math.h>

namespace {

constexpr int L    = 10;
constexpr int NH   = L * L;      // 100 harmonics
constexpr int NPB  = 64;         // threads per block (2 warps), 1 point/thread
constexpr int CHK  = NH / 4;     // 25 float4 chunks per point
constexpr int QSTR = 132;        // chunk-row stride: >=128 (row = 32 lanes x 4 floats)
                                 // and 132 mod 32 = 4 -> conflict-free in both phases
constexpr int WSLC = CHK * QSTR; // 3300 words per warp slice (13200 B)
constexpr double PI_D = 3.141592653589793238462643383279502884;

// ---- compile-time math (all constants folded to FFMA immediates) ----
constexpr double csqrt(double x) {
    double r = x > 1.0 ? x : 1.0;
    for (int i = 0; i < 100; ++i) r = 0.5 * (r + x / r);
    return r;
}
constexpr double factd(int n) {
    double r = 1.0;
    for (int i = 2; i <= n; ++i) r *= (double)i;
    return r;
}
constexpr double SQRT2_D = csqrt(2.0);
constexpr double Kd(int l, int m) {
    return csqrt((2.0 * l + 1.0) / (4.0 * PI_D) * factd(l - m) / factd(l + m));
}
constexpr double Kh(int l, int m) {
    return (m > 0 ? SQRT2_D : 1.0) * Kd(l, m);
}

struct Tabs {
    float k00;
    float dm[L];
    float em[L];
    float A[L][L];
    float B[L][L];
};

constexpr Tabs make_tabs() {
    Tabs t{};
    t.k00 = (float)Kh(0, 0);
    for (int m = 1; m < L; ++m)
        t.dm[m] = (float)(-(2.0 * m - 1.0) * Kh(m, m) / Kh(m - 1, m - 1));
    for (int m = 0; m + 1 < L; ++m)
        t.em[m] = (float)((2.0 * m + 1.0) * Kh(m + 1, m) / Kh(m, m));
    for (int m = 0; m < L; ++m)
        for (int l = m + 2; l < L; ++l) {
            t.A[l][m] = (float)((2.0 * l - 1.0) / (double)(l - m) * Kh(l, m) / Kh(l - 1, m));
            t.B[l][m] = (float)(-(l + m - 1.0) / (double)(l - m) * Kh(l, m) / Kh(l - 2, m));
        }
    return t;
}
constexpr Tabs TB = make_tabs();

template <int I> struct IC { static constexpr int v = I; };
template <int S, int E, class F>
__device__ __forceinline__ void unrolled(F&& f) {
    if constexpr (S < E) {
        f(IC<S>{});
        unrolled<S + 1, E>(static_cast<F&&>(f));
    }
}

} // namespace

__global__ __launch_bounds__(NPB) void sh_kernel(const float2* __restrict__ ll,
                                                 float* __restrict__ out, int N) {
    __shared__ __align__(16) float smbuf[(NPB / 32) * WSLC];   // 2 * 13200 B = 26400 B

    const int t    = threadIdx.x;
    const int lane = t & 31;
    float* sw      = smbuf + (t >> 5) * WSLC;          // this warp's slice
    const int p0   = blockIdx.x * NPB + (t & ~31);     // first point of this warp
    const int p    = p0 + lane;

    // ---------------- compute phase: all 100 values into registers ----------------
    float y[NH];

    {
        float2 v = (p < N) ? ll[p] : ll[0];
        const float phi = (v.x + 180.0f) * 0.017453292519943295f;
        const float th  = (v.y + 90.0f)  * 0.017453292519943295f;
        float s, x, s1, c1;
        __sincosf(th,  &s,  &x);     // s = sin(theta), x = cos(theta)
        __sincosf(phi, &s1, &c1);

        float Qmm = 0.0f;
        float cm = 1.0f, smv = 0.0f;

        unrolled<0, L>([&](auto mI) {
            constexpr int m = decltype(mI)::v;

            if constexpr (m == 0) {
                Qmm = TB.k00;
            } else if constexpr (m == 1) {
                constexpr float d = TB.dm[1];
                Qmm = d * (s * Qmm);
                cm = c1; smv = s1;
            } else {
                constexpr float d = TB.dm[m];
                Qmm = d * (s * Qmm);
                const float cn = fmaf(cm, c1, -(smv * s1));
                const float sn = fmaf(smv, c1,  (cm * s1));
                cm = cn; smv = sn;
            }

            if constexpr (m == 0) {
                y[0] = Qmm;
            } else {
                y[m * m + 2 * m] = Qmm * cm;
                y[m * m]         = Qmm * smv;
            }

            if constexpr (m + 1 < L) {
                constexpr float e = TB.em[m];
                float Q1 = e * (x * Qmm);
                constexpr int l1 = m + 1;
                if constexpr (m == 0) {
                    y[l1 * l1 + l1] = Q1;
                } else {
                    y[l1 * l1 + l1 + m] = Q1 * cm;
                    y[l1 * l1 + l1 - m] = Q1 * smv;
                }
                float Q2 = Qmm;
                unrolled<m + 2, L>([&](auto lI) {
                    constexpr int l = decltype(lI)::v;
                    constexpr float a = TB.A[l][m];
                    constexpr float b = TB.B[l][m];
                    const float Qn = fmaf(x * Q1, a, b * Q2);
                    if constexpr (m == 0) {
                        y[l * l + l] = Qn;
                    } else {
                        y[l * l + l + m] = Qn * cm;
                        y[l * l + l - m] = Qn * smv;
                    }
                    Q2 = Q1; Q1 = Qn;
                });
            }
        });
    }

    // 25 x STS.128, chunk-major layout: sw[q*QSTR + lane*4 .. +3]
    unrolled<0, CHK>([&](auto qI) {
        constexpr int q = decltype(qI)::v;
        *reinterpret_cast<float4*>(sw + q * QSTR + lane * 4) =
            make_float4(y[4 * q], y[4 * q + 1], y[4 * q + 2], y[4 * q + 3]);
    });

    __syncwarp();

    // ---------------- copy phase: 25 x (LDS.128 + STG.128), fully coalesced ----------------
    float* og = out + (size_t)p0 * NH;

    if (p0 + 32 <= N) {
        #pragma unroll 5
        for (int i = 0; i < CHK; ++i) {
            const int k  = i * 32 + lane;     // flat float4 index within tile (0..799)
            const int pf = k / 25;
            const int q  = k - pf * 25;
            const float4 v = *reinterpret_cast<const float4*>(sw + q * QSTR + pf * 4);
            __stcs(reinterpret_cast<float4*>(og + 4 * k), v);
        }
    } else {
        #pragma unroll 5
        for (int i = 0; i < CHK; ++i) {
            const int k  = i * 32 + lane;
            const int pf = k / 25;
            const int q  = k - pf * 25;
            if (p0 + pf < N) {
                const float4 v = *reinterpret_cast<const float4*>(sw + q * QSTR + pf * 4);
                __stcs(reinterpret_cast<float4*>(og + 4 * k), v);
            }
        }
    }
}

extern "C" void kernel_launch(void* const* d_in, const int* in_sizes, int n_in,
                              void* d_out, int out_size) {
    const float2* ll = (const float2*)d_in[0];
    float* out = (float*)d_out;
    const int N = in_sizes[0] / 2;
    const int grid = (N + NPB - 1) / NPB;
    sh_kernel<<<grid, NPB>>>(ll, out, N);
}